// round 14
// baseline (speedup 1.0000x reference)
#include <cuda_runtime.h>
#include <cuda_bf16.h>
#include <cstdint>

// Problem constants (SheafGluingPoly: B=4, M=50000, D=8, E=1600000, POLY_K=3, LAM=1)
#define B_CONST 4
#define D_CONST 8
#define MAX_MBD 1600000   // B*M*D
#define MAX_E   1600000

#define ETPB 256          // edge kernel: 8 warps/block, 8 edges/warp = 64 edges/block
#define EDGES_PER_BLK 64
#define EDGE_STRIDE 288   // smem bytes per edge (72 words; +16B rot for g>=4)
#define D_REGION (EDGES_PER_BLK * EDGE_STRIDE)   // 18432

// Scratch: ping-pong vertex state in [m][d][b] layout (b fastest; 128B/vertex),
// plus packed (src,dst) pairs.
__device__ float g_bufA[MAX_MBD];
__device__ float g_bufB[MAX_MBD];
__device__ int2  g_pair[MAX_E];

__device__ __forceinline__ unsigned smem_u32(const void* p)
{
    unsigned a;
    asm("{ .reg .u64 t; cvta.to.shared.u64 t, %1; cvt.u32.u64 %0, t; }"
        : "=r"(a) : "l"(p));
    return a;
}

__device__ __forceinline__ float4 shfl4(float4 a, int m, unsigned mask)
{
    float4 r;
    r.x = __shfl_xor_sync(mask, a.x, m);
    r.y = __shfl_xor_sync(mask, a.y, m);
    r.z = __shfl_xor_sync(mask, a.z, m);
    r.w = __shfl_xor_sync(mask, a.w, m);
    return r;
}
__device__ __forceinline__ void add4(float4& a, float4 b)
{
    a.x += b.x; a.y += b.y; a.z += b.z; a.w += b.w;
}
__device__ __forceinline__ void fma4(float4& acc, float s, float4 r)
{
    acc.x = fmaf(s, r.x, acc.x);
    acc.y = fmaf(s, r.y, acc.y);
    acc.z = fmaf(s, r.z, acc.z);
    acc.w = fmaf(s, r.w, acc.w);
}
__device__ __forceinline__ float4 mul4(float s, float4 r)
{
    return make_float4(s * r.x, s * r.y, s * r.z, s * r.w);
}

// forward partial over this lane's two dims:
__device__ __forceinline__ float4 zfwd(float2 S, float2 Dd,
                                       float4 psl, float4 psh,
                                       float4 pdl, float4 pdh)
{
    float4 z;
    z.x = fmaf(S.x, psl.x, fmaf(S.y, psh.x, -fmaf(Dd.x, pdl.x, Dd.y * pdh.x)));
    z.y = fmaf(S.x, psl.y, fmaf(S.y, psh.y, -fmaf(Dd.x, pdl.y, Dd.y * pdh.y)));
    z.z = fmaf(S.x, psl.z, fmaf(S.y, psh.z, -fmaf(Dd.x, pdl.z, Dd.y * pdh.z)));
    z.w = fmaf(S.x, psl.w, fmaf(S.y, psh.w, -fmaf(Dd.x, pdl.w, Dd.y * pdh.w)));
    return z;
}

// Vector float atomic reduction (sm_90+): one instruction, 16B.
__device__ __forceinline__ void red_add_v4(float* p, float4 v)
{
    asm volatile("red.global.add.v4.f32 [%0], {%1, %2, %3, %4};"
                 :: "l"(p), "f"(v.x), "f"(v.y), "f"(v.z), "f"(v.w)
                 : "memory");
}

// Blackwell 256-bit load (sm_100+): 8 floats, 32B-aligned.
__device__ __forceinline__ void ldg256(const float* p, float4& a, float4& b)
{
    asm volatile("ld.global.nc.v8.f32 {%0,%1,%2,%3,%4,%5,%6,%7}, [%8];"
                 : "=f"(a.x), "=f"(a.y), "=f"(a.z), "=f"(a.w),
                   "=f"(b.x), "=f"(b.y), "=f"(b.z), "=f"(b.w)
                 : "l"(p));
}

// Bulk async copy global->shared (TMA engine, no tensormap), 256B.
__device__ __forceinline__ void bulk_cp256(unsigned dst, const void* src,
                                           unsigned mbar)
{
    asm volatile(
        "cp.async.bulk.shared::cluster.global.mbarrier::complete_tx::bytes "
        "[%0], [%1], %2, [%3];"
        :: "r"(dst), "l"(src), "r"(256u), "r"(mbar) : "memory");
}

// ---------------------------------------------------------------------------
// init (fused with pair packing)
// ---------------------------------------------------------------------------
__global__ void init_kernel(const float* __restrict__ c0,
                            const int*   __restrict__ src,
                            const int*   __restrict__ dst,
                            const float* __restrict__ pc,
                            float* __restrict__ out,
                            float* __restrict__ v,
                            float* __restrict__ accz,
                            int2*  __restrict__ pair,
                            int M, int E)
{
    int i = blockIdx.x * blockDim.x + threadIdx.x;
    int n = M * 32;
    if (i < n) {
        int m = i >> 5;
        int d = (i >> 2) & 7;
        int b = i & 3;
        int src_idx = (b * M + m) * 8 + d;   // [b][m][d] layout of c0 / out
        float val = c0[src_idx];
        v[i] = val;
        out[src_idx] = pc[0] * val;
        accz[i] = 0.0f;
    }
    if (i < E) {
        pair[i] = make_int2(src[i], dst[i]);
    }
}

// ---------------------------------------------------------------------------
// edge kernel: 64 edges/block, 8 edges/warp, 4 lanes/edge (g=t>>2, c=t&3).
//
// R path: per-edge 256B cp.async.bulk into smem at stride 288B, with a 16B
// rotation for edges with (g&4) -> sigma-layout LDS.64 reads are verifiably
// conflict-free (bank = 8*((g+((k&3)^c)) mod 4) + 2c + 4*[g>=4], injective
// over the 32 lanes for every k). No LDG, no STS: R bypasses L1/RF entirely.
//
// Compute (identical to R13): lane owns dims {2c,2c+1} x 4 batches;
// reduce-scatter 6 shfl4 -> z0=r[c], z4=r[c+4]; allgather 6 shfl4; local
// transpose matvec; 4 red.v4 per lane.
// ---------------------------------------------------------------------------
__global__ void __launch_bounds__(ETPB, 4)
edge_kernel(const float* __restrict__ v,
            const int2*  __restrict__ pair,
            const float* __restrict__ Rsrc,
            const float* __restrict__ Rdst,
            float*       __restrict__ acc,
            int E)
{
    __shared__ __align__(128) char tile[2 * D_REGION];   // 36864B
    __shared__ __align__(8) unsigned long long mbar_s;

    int tidb = threadIdx.x;
    unsigned tbase = smem_u32(tile);
    unsigned mbar  = smem_u32(&mbar_s);

    int e0blk = blockIdx.x * EDGES_PER_BLK;
    int nAct = E - e0blk;
    if (nAct > EDGES_PER_BLK) nAct = EDGES_PER_BLK;

    if (tidb == 0) {
        asm volatile("mbarrier.init.shared.b64 [%0], %1;"
                     :: "r"(mbar), "r"(1u) : "memory");
    }
    __syncthreads();
    if (tidb == 0) {
        unsigned tx = (unsigned)nAct * 512u;
        asm volatile("mbarrier.arrive.expect_tx.shared.b64 _, [%0], %1;"
                     :: "r"(mbar), "r"(tx) : "memory");
    }
    __syncthreads();   // expect_tx ordered before any complete_tx

    // threads 0..63: Rs edge l; threads 64..127: Rd edge l
    if (tidb < 128) {
        int l = tidb & 63;
        if (l < nAct) {
            bool isD = (tidb >= 64);
            const float* srcp = (isD ? Rdst : Rsrc) + (size_t)(e0blk + l) * 64;
            unsigned dst = tbase + (isD ? D_REGION : 0)
                         + (unsigned)l * EDGE_STRIDE + ((l & 4) ? 16u : 0u);
            bulk_cp256(dst, srcp, mbar);
        }
    }

    // wait for all bulk copies (parity 0), acquire ordering
    {
        unsigned done;
        asm volatile(
            "{\n\t.reg .pred p;\n\t"
            "mbarrier.try_wait.parity.acquire.cta.shared::cta.b64 p, [%1], 0;\n\t"
            "selp.b32 %0, 1, 0, p;\n\t}"
            : "=r"(done) : "r"(mbar) : "memory");
        if (!done) {
            asm volatile(
                "{\n\t.reg .pred P1;\n\t"
                "WL_%=:\n\t"
                "mbarrier.try_wait.parity.acquire.cta.shared::cta.b64 P1, [%0], 0, 0x989680;\n\t"
                "@P1 bra.uni WD_%=;\n\t"
                "bra.uni WL_%=;\n\t"
                "WD_%=:\n\t}"
                :: "r"(mbar) : "memory");
        }
    }

    int t = tidb & 31;
    int wid = tidb >> 5;
    int g = t >> 2;
    int c = t & 3;
    int l = wid * 8 + g;            // edge local index
    int e = e0blk + l;

    bool act = (e < E);
    int eC = act ? e : (E > 0 ? E - 1 : 0);
    int2 pr = __ldg(pair + eC);

    // vertex loads: dims 2c,2c+1 x 4 batches = 32B each side
    float4 psl, psh, pdl, pdh;
    ldg256(v + pr.x * 32 + c * 8, psl, psh);
    ldg256(v + pr.y * 32 + c * 8, pdl, pdh);

    // sigma-layout column-pair reads straight from the TMA tile
    float2 S2[8], D2[8];
    {
        unsigned sb = tbase + (unsigned)l * EDGE_STRIDE + ((g & 4) ? 16u : 0u)
                    + (unsigned)c * 8u;
#pragma unroll
        for (int k = 0; k < 8; k++) {
            unsigned a = (((unsigned)k & 3u) ^ (unsigned)c) | ((unsigned)k & 4u);
            unsigned ad = sb + a * 32u;
            asm volatile("ld.shared.v2.f32 {%0,%1}, [%4]; ld.shared.v2.f32 {%2,%3}, [%5];"
                         : "=f"(S2[k].x), "=f"(S2[k].y), "=f"(D2[k].x), "=f"(D2[k].y)
                         : "r"(ad), "r"(ad + (unsigned)D_REGION));
        }
    }

    const unsigned qm = 0xFu << (t & 28);   // 4-lane reduction group

    // fused forward + reduce-scatter (6 shfl4)
    float4 z0, z4;
    {
        z0 = zfwd(S2[0], D2[0], psl, psh, pdl, pdh);
        float4 z1 = zfwd(S2[1], D2[1], psl, psh, pdl, pdh);
        add4(z0, shfl4(z1, 1, qm));
        float4 z2 = zfwd(S2[2], D2[2], psl, psh, pdl, pdh);
        float4 z3 = zfwd(S2[3], D2[3], psl, psh, pdl, pdh);
        add4(z2, shfl4(z3, 1, qm));
        add4(z0, shfl4(z2, 2, qm));      // z0 = r[c][:]
        z4 = zfwd(S2[4], D2[4], psl, psh, pdl, pdh);
        float4 z5 = zfwd(S2[5], D2[5], psl, psh, pdl, pdh);
        add4(z4, shfl4(z5, 1, qm));
        float4 z6 = zfwd(S2[6], D2[6], psl, psh, pdl, pdh);
        float4 z7 = zfwd(S2[7], D2[7], psl, psh, pdl, pdh);
        add4(z6, shfl4(z7, 1, qm));
        add4(z4, shfl4(z6, 2, qm));      // z4 = r[c+4][:]
    }

    // allgather (6 shfl4) + local transpose matvec
    float4 csl = mul4(S2[0].x, z0), csh = mul4(S2[0].y, z0);
    float4 cdl = mul4(D2[0].x, z0), cdh = mul4(D2[0].y, z0);
    fma4(csl, S2[4].x, z4);  fma4(csh, S2[4].y, z4);
    fma4(cdl, D2[4].x, z4);  fma4(cdh, D2[4].y, z4);
#pragma unroll
    for (int x = 1; x < 4; x++) {
        float4 r0 = shfl4(z0, x, qm);    // r[x^c][:]
        float4 r1 = shfl4(z4, x, qm);    // r[(x^c)+4][:]
        fma4(csl, S2[x].x, r0);      fma4(csh, S2[x].y, r0);
        fma4(cdl, D2[x].x, r0);      fma4(cdh, D2[x].y, r0);
        fma4(csl, S2[x + 4].x, r1);  fma4(csh, S2[x + 4].y, r1);
        fma4(cdl, D2[x + 4].x, r1);  fma4(cdh, D2[x + 4].y, r1);
    }

    if (act) {
        float* as = acc + pr.x * 32 + c * 8;
        red_add_v4(as,     csl);
        red_add_v4(as + 4, csh);
        float* ad = acc + pr.y * 32 + c * 8;
        red_add_v4(ad,     make_float4(-cdl.x, -cdl.y, -cdl.z, -cdl.w));
        red_add_v4(ad + 4, make_float4(-cdh.x, -cdh.y, -cdh.z, -cdh.w));
    }
}

// ---------------------------------------------------------------------------
// update: out[b][m][d] += pc[k] * acc[m][d][b]; optionally zero other buffer
// ---------------------------------------------------------------------------
__global__ void update_kernel(const float* __restrict__ acc,
                              const float* __restrict__ pc,
                              int k,
                              float* __restrict__ out,
                              float* __restrict__ zother,
                              int M)
{
    int i = blockIdx.x * blockDim.x + threadIdx.x;
    int n = M * 32;
    if (i >= n) return;
    int m = i >> 5;
    int d = (i >> 2) & 7;
    int b = i & 3;
    float val = acc[i];
    int oi = (b * M + m) * 8 + d;
    out[oi] += pc[k] * val;
    if (zother) zother[i] = 0.0f;
}

// ---------------------------------------------------------------------------
// launch  (7 launches total; ncu -s 5 captures launch #6 = 3rd edge_kernel)
// ---------------------------------------------------------------------------
extern "C" void kernel_launch(void* const* d_in, const int* in_sizes, int n_in,
                              void* d_out, int out_size)
{
    const float* c0  = (const float*)d_in[0];
    const int*   src = (const int*)  d_in[1];
    const int*   dst = (const int*)  d_in[2];
    const float* Rs  = (const float*)d_in[3];
    const float* Rd  = (const float*)d_in[4];
    const float* pc  = (const float*)d_in[5];
    float* out = (float*)d_out;

    int E = in_sizes[1];
    int M = in_sizes[0] / (B_CONST * D_CONST);

    float* bufA;  float* bufB;  int2* pairp;
    cudaGetSymbolAddress((void**)&bufA,  g_bufA);
    cudaGetSymbolAddress((void**)&bufB,  g_bufB);
    cudaGetSymbolAddress((void**)&pairp, g_pair);

    int nV = M * 32;
    int tb = 256;
    int nInit = (nV > E) ? nV : E;
    int gI = (nInit + tb - 1) / tb;
    int gV = (nV + tb - 1) / tb;
    int gE = (E + EDGES_PER_BLK - 1) / EDGES_PER_BLK;

    init_kernel<<<gI, tb>>>(c0, src, dst, pc, out, bufA, bufB, pairp, M, E);

    // k = 1: B <- L(A); out += pc[1]*B; zero A
    edge_kernel<<<gE, ETPB>>>(bufA, pairp, Rs, Rd, bufB, E);
    update_kernel<<<gV, tb>>>(bufB, pc, 1, out, bufA, M);

    // k = 2: A <- L(B); out += pc[2]*A; zero B
    edge_kernel<<<gE, ETPB>>>(bufB, pairp, Rs, Rd, bufA, E);
    update_kernel<<<gV, tb>>>(bufA, pc, 2, out, bufB, M);

    // k = 3: B <- L(A); out += pc[3]*B
    edge_kernel<<<gE, ETPB>>>(bufA, pairp, Rs, Rd, bufB, E);
    update_kernel<<<gV, tb>>>(bufB, pc, 3, out, nullptr, M);
}

// round 15
// speedup vs baseline: 1.2759x; 1.2759x over previous
#include <cuda_runtime.h>
#include <cuda_bf16.h>
#include <cstdint>

// Problem constants (SheafGluingPoly: B=4, M=50000, D=8, E=1600000, POLY_K=3, LAM=1)
#define B_CONST 4
#define D_CONST 8
#define MAX_MBD 1600000   // B*M*D
#define MAX_E   1600000

#define ETPB 256            // 8 warps/block, 8 edges/warp = 64 edges/block
#define EDGES_PER_BLK 64
#define R_BYTES (EDGES_PER_BLK * 256)   // 16384 per matrix

// Scratch: ping-pong vertex state in [m][d][b] layout (b fastest; 128B/vertex),
// plus packed (src,dst) pairs.
__device__ float g_bufA[MAX_MBD];
__device__ float g_bufB[MAX_MBD];
__device__ int2  g_pair[MAX_E];

__device__ __forceinline__ unsigned smem_u32(const void* p)
{
    unsigned a;
    asm("{ .reg .u64 t; cvta.to.shared.u64 t, %1; cvt.u32.u64 %0, t; }"
        : "=r"(a) : "l"(p));
    return a;
}

__device__ __forceinline__ float4 shfl4(float4 a, int m, unsigned mask)
{
    float4 r;
    r.x = __shfl_xor_sync(mask, a.x, m);
    r.y = __shfl_xor_sync(mask, a.y, m);
    r.z = __shfl_xor_sync(mask, a.z, m);
    r.w = __shfl_xor_sync(mask, a.w, m);
    return r;
}
__device__ __forceinline__ void add4(float4& a, float4 b)
{
    a.x += b.x; a.y += b.y; a.z += b.z; a.w += b.w;
}
__device__ __forceinline__ void fma4(float4& acc, float s, float4 r)
{
    acc.x = fmaf(s, r.x, acc.x);
    acc.y = fmaf(s, r.y, acc.y);
    acc.z = fmaf(s, r.z, acc.z);
    acc.w = fmaf(s, r.w, acc.w);
}
__device__ __forceinline__ float4 mul4(float s, float4 r)
{
    return make_float4(s * r.x, s * r.y, s * r.z, s * r.w);
}

// forward partial over this lane's two dims
__device__ __forceinline__ float4 zfwd(float2 S, float2 Dd,
                                       float4 psl, float4 psh,
                                       float4 pdl, float4 pdh)
{
    float4 z;
    z.x = fmaf(S.x, psl.x, fmaf(S.y, psh.x, -fmaf(Dd.x, pdl.x, Dd.y * pdh.x)));
    z.y = fmaf(S.x, psl.y, fmaf(S.y, psh.y, -fmaf(Dd.x, pdl.y, Dd.y * pdh.y)));
    z.z = fmaf(S.x, psl.z, fmaf(S.y, psh.z, -fmaf(Dd.x, pdl.z, Dd.y * pdh.z)));
    z.w = fmaf(S.x, psl.w, fmaf(S.y, psh.w, -fmaf(Dd.x, pdl.w, Dd.y * pdh.w)));
    return z;
}

// Vector float atomic reduction (sm_90+): one instruction, 16B.
__device__ __forceinline__ void red_add_v4(float* p, float4 v)
{
    asm volatile("red.global.add.v4.f32 [%0], {%1, %2, %3, %4};"
                 :: "l"(p), "f"(v.x), "f"(v.y), "f"(v.z), "f"(v.w)
                 : "memory");
}

// Blackwell 256-bit load (sm_100+): 8 floats, 32B-aligned.
__device__ __forceinline__ void ldg256(const float* p, float4& a, float4& b)
{
    asm volatile("ld.global.nc.v8.f32 {%0,%1,%2,%3,%4,%5,%6,%7}, [%8];"
                 : "=f"(a.x), "=f"(a.y), "=f"(a.z), "=f"(a.w),
                   "=f"(b.x), "=f"(b.y), "=f"(b.z), "=f"(b.w)
                 : "l"(p));
}

// Bulk async copy global->shared (TMA engine), arbitrary 16B-multiple size.
__device__ __forceinline__ void bulk_cp(unsigned dst, const void* src,
                                        unsigned bytes, unsigned mbar)
{
    asm volatile(
        "cp.async.bulk.shared::cluster.global.mbarrier::complete_tx::bytes "
        "[%0], [%1], %2, [%3];"
        :: "r"(dst), "l"(src), "r"(bytes), "r"(mbar) : "memory");
}

// ---------------------------------------------------------------------------
// init (fused with pair packing)
// ---------------------------------------------------------------------------
__global__ void init_kernel(const float* __restrict__ c0,
                            const int*   __restrict__ src,
                            const int*   __restrict__ dst,
                            const float* __restrict__ pc,
                            float* __restrict__ out,
                            float* __restrict__ v,
                            float* __restrict__ accz,
                            int2*  __restrict__ pair,
                            int M, int E)
{
    int i = blockIdx.x * blockDim.x + threadIdx.x;
    int n = M * 32;
    if (i < n) {
        int m = i >> 5;
        int d = (i >> 2) & 7;
        int b = i & 3;
        int src_idx = (b * M + m) * 8 + d;   // [b][m][d] layout of c0 / out
        float val = c0[src_idx];
        v[i] = val;
        out[src_idx] = pc[0] * val;
        accz[i] = 0.0f;
    }
    if (i < E) {
        pair[i] = make_int2(src[i], dst[i]);
    }
}

// ---------------------------------------------------------------------------
// edge kernel: 64 edges/block, 8 edges/warp, 4 lanes/edge (g=t>>2, c=t&3).
//
// R path: TWO cp.async.bulk per block (Rs 16KB, Rd 16KB, contiguous, RAW
// layout). Bank conflicts are eliminated not by layout but by the phi-relabel:
//   register k at lane (g,c) holds row a_k(c) = ((k&3) ^ c ^ (g&3)) | (k&4).
// XOR by the per-edge constant phi=g&3 is an automorphism of the reduction
// (phi cancels in every shuffle pairing), and makes the 8B LDS position
// p = 4((k&3)^c^phi)+c distinct within each 16-lane phase -> 2-cycle floor.
//
// Compute identical to R13: reduce-scatter 6 shfl4 -> z0=r[c^phi... structure
// unchanged], allgather 6 shfl4, local transpose matvec, 4 red.v4 per lane.
// v/pair loads issued BEFORE the TMA wait to overlap fetch latency.
// ---------------------------------------------------------------------------
__global__ void __launch_bounds__(ETPB, 4)
edge_kernel(const float* __restrict__ v,
            const int2*  __restrict__ pair,
            const float* __restrict__ Rsrc,
            const float* __restrict__ Rdst,
            float*       __restrict__ acc,
            int E)
{
    __shared__ __align__(128) char tile[2 * R_BYTES];   // 32KB raw
    __shared__ __align__(8) unsigned long long mbar_s;

    int tidb = threadIdx.x;
    unsigned mbar = smem_u32(&mbar_s);

    int e0blk = blockIdx.x * EDGES_PER_BLK;
    int nAct = E - e0blk;
    if (nAct > EDGES_PER_BLK) nAct = EDGES_PER_BLK;

    if (tidb == 0) {
        asm volatile("mbarrier.init.shared.b64 [%0], %1;"
                     :: "r"(mbar), "r"(1u) : "memory");
    }
    __syncthreads();
    if (tidb == 0) {
        unsigned bytes = (unsigned)nAct * 256u;
        asm volatile("mbarrier.arrive.expect_tx.shared.b64 _, [%0], %1;"
                     :: "r"(mbar), "r"(bytes * 2u) : "memory");
        unsigned tbase = smem_u32(tile);
        bulk_cp(tbase,           Rsrc + (size_t)e0blk * 64, bytes, mbar);
        bulk_cp(tbase + R_BYTES, Rdst + (size_t)e0blk * 64, bytes, mbar);
    }

    int t = tidb & 31;
    int wid = tidb >> 5;
    int g = t >> 2;
    int c = t & 3;
    int l = wid * 8 + g;            // edge local index
    int e = e0blk + l;

    bool act = (e < E);
    int eC = act ? e : (E > 0 ? E - 1 : 0);

    // independent loads BEFORE the TMA wait (overlap fetch latency)
    int2 pr = __ldg(pair + eC);
    float4 psl, psh, pdl, pdh;
    ldg256(v + pr.x * 32 + c * 8, psl, psh);
    ldg256(v + pr.y * 32 + c * 8, pdl, pdh);

    // wait for both bulk copies (parity 0), acquire ordering
    {
        unsigned done;
        asm volatile(
            "{\n\t.reg .pred p;\n\t"
            "mbarrier.try_wait.parity.acquire.cta.shared::cta.b64 p, [%1], 0;\n\t"
            "selp.b32 %0, 1, 0, p;\n\t}"
            : "=r"(done) : "r"(mbar) : "memory");
        if (!done) {
            asm volatile(
                "{\n\t.reg .pred P1;\n\t"
                "WL_%=:\n\t"
                "mbarrier.try_wait.parity.acquire.cta.shared::cta.b64 P1, [%0], 0, 0x989680;\n\t"
                "@P1 bra.uni WD_%=;\n\t"
                "bra.uni WL_%=;\n\t"
                "WD_%=:\n\t}"
                :: "r"(mbar) : "memory");
        }
    }

    // phi-relabeled column-pair reads from the RAW tile (conflict-free)
    float2 S2[8], D2[8];
    {
        unsigned cg = (unsigned)(c ^ (g & 3));
        const char* sbS = tile + l * 256 + c * 8;
        const char* sbD = sbS + R_BYTES;
#pragma unroll
        for (int k = 0; k < 8; k++) {
            unsigned off = ((((unsigned)k & 3u) ^ cg) << 5)
                         + (((unsigned)k & 4u) ? 128u : 0u);
            S2[k] = *(const float2*)(sbS + off);
            D2[k] = *(const float2*)(sbD + off);
        }
    }

    const unsigned qm = 0xFu << (t & 28);   // 4-lane reduction group

    // fused forward + reduce-scatter (6 shfl4)  [phi cancels: code = R13]
    float4 z0, z4;
    {
        z0 = zfwd(S2[0], D2[0], psl, psh, pdl, pdh);
        float4 z1 = zfwd(S2[1], D2[1], psl, psh, pdl, pdh);
        add4(z0, shfl4(z1, 1, qm));
        float4 z2 = zfwd(S2[2], D2[2], psl, psh, pdl, pdh);
        float4 z3 = zfwd(S2[3], D2[3], psl, psh, pdl, pdh);
        add4(z2, shfl4(z3, 1, qm));
        add4(z0, shfl4(z2, 2, qm));
        z4 = zfwd(S2[4], D2[4], psl, psh, pdl, pdh);
        float4 z5 = zfwd(S2[5], D2[5], psl, psh, pdl, pdh);
        add4(z4, shfl4(z5, 1, qm));
        float4 z6 = zfwd(S2[6], D2[6], psl, psh, pdl, pdh);
        float4 z7 = zfwd(S2[7], D2[7], psl, psh, pdl, pdh);
        add4(z6, shfl4(z7, 1, qm));
        add4(z4, shfl4(z6, 2, qm));
    }

    // allgather (6 shfl4) + local transpose matvec
    float4 csl = mul4(S2[0].x, z0), csh = mul4(S2[0].y, z0);
    float4 cdl = mul4(D2[0].x, z0), cdh = mul4(D2[0].y, z0);
    fma4(csl, S2[4].x, z4);  fma4(csh, S2[4].y, z4);
    fma4(cdl, D2[4].x, z4);  fma4(cdh, D2[4].y, z4);
#pragma unroll
    for (int x = 1; x < 4; x++) {
        float4 r0 = shfl4(z0, x, qm);
        float4 r1 = shfl4(z4, x, qm);
        fma4(csl, S2[x].x, r0);      fma4(csh, S2[x].y, r0);
        fma4(cdl, D2[x].x, r0);      fma4(cdh, D2[x].y, r0);
        fma4(csl, S2[x + 4].x, r1);  fma4(csh, S2[x + 4].y, r1);
        fma4(cdl, D2[x + 4].x, r1);  fma4(cdh, D2[x + 4].y, r1);
    }

    if (act) {
        float* as = acc + pr.x * 32 + c * 8;
        red_add_v4(as,     csl);
        red_add_v4(as + 4, csh);
        float* ad = acc + pr.y * 32 + c * 8;
        red_add_v4(ad,     make_float4(-cdl.x, -cdl.y, -cdl.z, -cdl.w));
        red_add_v4(ad + 4, make_float4(-cdh.x, -cdh.y, -cdh.z, -cdh.w));
    }
}

// ---------------------------------------------------------------------------
// update: out[b][m][d] += pc[k] * acc[m][d][b]; optionally zero other buffer
// ---------------------------------------------------------------------------
__global__ void update_kernel(const float* __restrict__ acc,
                              const float* __restrict__ pc,
                              int k,
                              float* __restrict__ out,
                              float* __restrict__ zother,
                              int M)
{
    int i = blockIdx.x * blockDim.x + threadIdx.x;
    int n = M * 32;
    if (i >= n) return;
    int m = i >> 5;
    int d = (i >> 2) & 7;
    int b = i & 3;
    float val = acc[i];
    int oi = (b * M + m) * 8 + d;
    out[oi] += pc[k] * val;
    if (zother) zother[i] = 0.0f;
}

// ---------------------------------------------------------------------------
// launch  (7 launches total; ncu -s 5 captures launch #6 = 3rd edge_kernel)
// ---------------------------------------------------------------------------
extern "C" void kernel_launch(void* const* d_in, const int* in_sizes, int n_in,
                              void* d_out, int out_size)
{
    const float* c0  = (const float*)d_in[0];
    const int*   src = (const int*)  d_in[1];
    const int*   dst = (const int*)  d_in[2];
    const float* Rs  = (const float*)d_in[3];
    const float* Rd  = (const float*)d_in[4];
    const float* pc  = (const float*)d_in[5];
    float* out = (float*)d_out;

    int E = in_sizes[1];
    int M = in_sizes[0] / (B_CONST * D_CONST);

    float* bufA;  float* bufB;  int2* pairp;
    cudaGetSymbolAddress((void**)&bufA,  g_bufA);
    cudaGetSymbolAddress((void**)&bufB,  g_bufB);
    cudaGetSymbolAddress((void**)&pairp, g_pair);

    int nV = M * 32;
    int tb = 256;
    int nInit = (nV > E) ? nV : E;
    int gI = (nInit + tb - 1) / tb;
    int gV = (nV + tb - 1) / tb;
    int gE = (E + EDGES_PER_BLK - 1) / EDGES_PER_BLK;

    init_kernel<<<gI, tb>>>(c0, src, dst, pc, out, bufA, bufB, pairp, M, E);

    // k = 1: B <- L(A); out += pc[1]*B; zero A
    edge_kernel<<<gE, ETPB>>>(bufA, pairp, Rs, Rd, bufB, E);
    update_kernel<<<gV, tb>>>(bufB, pc, 1, out, bufA, M);

    // k = 2: A <- L(B); out += pc[2]*A; zero B
    edge_kernel<<<gE, ETPB>>>(bufB, pairp, Rs, Rd, bufA, E);
    update_kernel<<<gV, tb>>>(bufA, pc, 2, out, bufB, M);

    // k = 3: B <- L(A); out += pc[3]*B
    edge_kernel<<<gE, ETPB>>>(bufA, pairp, Rs, Rd, bufB, E);
    update_kernel<<<gV, tb>>>(bufB, pc, 3, out, nullptr, M);
}